// round 15
// baseline (speedup 1.0000x reference)
#include <cuda_runtime.h>
#include <cuda_bf16.h>
#include <cuda_fp16.h>
#include <math.h>
#include <stdint.h>

#define TT 512
#define BB 64
#define DH 1024
#define BH (BB*DH)
#define NB 128          // persistent blocks, 1/SM
#define CPB 8           // hidden columns per block

// ---------------- recurrent kernel SMEM layout (bytes) --------------------
// W slabs: 3 x 16384 (WR, WZ, WH) single fp16
#define RS_W    0
#define RS_A    49152      // 2 buffers x 65536 (fp16 h half: 64 rows x 1024B)
#define RS_ABUF 65536
#define RS_Z    180224     // z gate buf 64x8 f32
#define RS_TOT  182272

// ---------------- input gemm SMEM layout (bytes, per stage) ---------------
#define IG_A    0          // X fp16: 128 rows x 128B
#define IG_WH   16384      // W hi fp16: 64 rows x 512B
#define IG_WL   49152      // W lo fp16
#define IG_STG  81920
#define IG_TOT  163840

// ---------------- device globals ------------------------------------------
__device__ float g_Xr[(size_t)TT * BH];
__device__ float g_Xz[(size_t)TT * BH];
__device__ float g_Xh[(size_t)TT * BH];
__device__ __half g_X16[(size_t)TT * BB * DH];
__device__ __half g_W16h[3u * 1024u * 1024u];
__device__ __half g_W16l[3u * 1024u * 1024u];
__device__ float g_h_f32[BH];
__device__ __half g_h16[4][BH];      // 4-deep h exchange buffers (fp16)
__device__ __half g_Rh16[4][BH];     // 4-deep Rh exchange buffers (fp16)
__device__ unsigned g_cnt_h[2];      // h-warp-publish counters, per 512-col k-chunk
__device__ unsigned g_cnt_rh[2];     // Rh-warp-publish counters, per k-chunk
__device__ unsigned g_p1done;        // blocks done reading h (phase 1)
__device__ unsigned g_p2done;        // blocks done reading Rh (phase 2)
__device__ unsigned g_bar_count = 0;
__device__ volatile unsigned g_bar_gen = 0;

// ---------------- helpers -------------------------------------------------
__device__ __forceinline__ uint32_t smem_u32(const void* p) {
    uint32_t a;
    asm("{ .reg .u64 t; cvta.to.shared.u64 t, %1; cvt.u32.u64 %0, t; }" : "=r"(a) : "l"(p));
    return a;
}
__device__ __forceinline__ void mma16816h(float* c, const uint32_t* a, const uint32_t* b) {
    asm volatile("mma.sync.aligned.m16n8k16.row.col.f32.f16.f16.f32 "
        "{%0,%1,%2,%3}, {%4,%5,%6,%7}, {%8,%9}, {%0,%1,%2,%3};"
        : "+f"(c[0]), "+f"(c[1]), "+f"(c[2]), "+f"(c[3])
        : "r"(a[0]), "r"(a[1]), "r"(a[2]), "r"(a[3]), "r"(b[0]), "r"(b[1]));
}
__device__ __forceinline__ void ldsm_x4(uint32_t* r, uint32_t a) {
    asm volatile("ldmatrix.sync.aligned.m8n8.x4.shared.b16 {%0,%1,%2,%3}, [%4];"
        : "=r"(r[0]), "=r"(r[1]), "=r"(r[2]), "=r"(r[3]) : "r"(a));
}
__device__ __forceinline__ void ldsm_x4t(uint32_t* r, uint32_t a) {
    asm volatile("ldmatrix.sync.aligned.m8n8.x4.trans.shared.b16 {%0,%1,%2,%3}, [%4];"
        : "=r"(r[0]), "=r"(r[1]), "=r"(r[2]), "=r"(r[3]) : "r"(a));
}
#define CPASYNC16(dst, src) asm volatile("cp.async.cg.shared.global [%0], [%1], 16;" :: "r"(dst), "l"(src))
#define CPCOMMIT() asm volatile("cp.async.commit_group;" ::: "memory")
#define CPWAIT1()  asm volatile("cp.async.wait_group 1;" ::: "memory")
#define CPWAIT0()  asm volatile("cp.async.wait_group 0;" ::: "memory")

__device__ __forceinline__ unsigned ld_acq_g(const unsigned* p) {
    unsigned v;
    asm volatile("ld.acquire.gpu.global.u32 %0, [%1];" : "=r"(v) : "l"(p) : "memory");
    return v;
}
__device__ __forceinline__ void waitGE(const unsigned* p, unsigned tgt) {
    while ((int)(ld_acq_g(p) - tgt) < 0) { }
}
__device__ __forceinline__ void red_rel_gpu(unsigned* p, unsigned v) {
    asm volatile("red.release.gpu.global.add.u32 [%0], %1;" :: "l"(p), "r"(v) : "memory");
}

__device__ __forceinline__ uint32_t packh(float x, float y) {
    __half2 hh = __floats2half2_rn(x, y);
    return *(uint32_t*)&hh;
}
__device__ __forceinline__ float sigf(float x) { return 1.0f / (1.0f + expf(-x)); }
__device__ __forceinline__ uint32_t swz32(uint32_t s, uint32_t r) {
    return ((s & 7u) ^ (r & 7u)) | (s & 24u);
}
// general swizzle for rows made of up to 64 16B segs
__device__ __forceinline__ uint32_t swzg(uint32_t s, uint32_t r) {
    return ((s & 7u) ^ (r & 7u)) | (s & ~7u);
}

// ---------------- grid barrier (init only) --------------------------------
__device__ __forceinline__ void gridBarrier() {
    __syncthreads();
    if (threadIdx.x == 0) {
        __threadfence();
        unsigned g = g_bar_gen;
        if (atomicAdd(&g_bar_count, 1u) == (unsigned)(NB - 1)) {
            g_bar_count = 0;
            __threadfence();
            g_bar_gen = g + 1;
        } else {
            while (g_bar_gen == g) { }
        }
        __threadfence();
    }
    __syncthreads();
}

// ---------------- prepass: fp32 -> fp16 single ----------------------------
__global__ void __launch_bounds__(256) split_h1(
    const float* __restrict__ src, __half* __restrict__ dst, int n4)
{
    int i = blockIdx.x * 256 + threadIdx.x;
    if (i >= n4) return;
    float4 v = __ldg((const float4*)src + i);
    ((uint2*)dst)[i] = make_uint2(packh(v.x, v.y), packh(v.z, v.w));
}

// ---------------- prepass: fp32 -> fp16 hi/lo split -----------------------
__global__ void __launch_bounds__(256) split_h2(
    const float* __restrict__ src, __half* __restrict__ hi,
    __half* __restrict__ lo, int n4)
{
    int i = blockIdx.x * 256 + threadIdx.x;
    if (i >= n4) return;
    float4 v = __ldg((const float4*)src + i);
    float f[4] = { v.x, v.y, v.z, v.w };
    uint32_t hh[2], ll[2];
    #pragma unroll
    for (int q = 0; q < 2; q++) {
        __half h0 = __float2half_rn(f[q*2]),   h1 = __float2half_rn(f[q*2+1]);
        __half l0 = __float2half_rn(f[q*2]   - __half2float(h0));
        __half l1 = __float2half_rn(f[q*2+1] - __half2float(h1));
        __half2 ph = __halves2half2(h0, h1), pl = __halves2half2(l0, l1);
        hh[q] = *(uint32_t*)&ph; ll[q] = *(uint32_t*)&pl;
    }
    ((uint2*)hi)[i] = make_uint2(hh[0], hh[1]);
    ((uint2*)lo)[i] = make_uint2(ll[0], ll[1]);
}

// ---------------- input projection GEMM (fp16 HMMA, cp.async pipeline) ----
__global__ void __launch_bounds__(512, 1) input_gemm(
    const float* __restrict__ br, const float* __restrict__ bz, const float* __restrict__ bh)
{
    extern __shared__ char sm[];
    const uint32_t sb = smem_u32(sm);
    const int z = blockIdx.z;
    const float* bias = (z == 0) ? br : (z == 1) ? bz : bh;
    float* Out = (z == 0) ? g_Xr : (z == 1) ? g_Xz : g_Xh;
    const __half* WHi = g_W16h + (size_t)z * 1048576u;
    const __half* WLo = g_W16l + (size_t)z * 1048576u;

    const int tid = threadIdx.x;
    const int lane = tid & 31, w = tid >> 5;
    const int rowBase = blockIdx.y * 128;
    const int colBase = blockIdx.x * 256;
    const int mw = (w & 3) * 32;
    const int nw = (w >> 2) * 64;

    float acc[2][8][4];
    #pragma unroll
    for (int i = 0; i < 2; i++)
        #pragma unroll
        for (int j = 0; j < 8; j++)
            #pragma unroll
            for (int q = 0; q < 4; q++) acc[i][j][q] = 0.f;

    auto stage = [&](int c, uint32_t bufSm) {
        const int k0 = c * 64;
        #pragma unroll
        for (int it = 0; it < 2; it++) {
            int idx = tid + it * 512;
            int r = idx >> 3, s = idx & 7;
            uint32_t d = bufSm + IG_A + r * 128 + ((s ^ (r & 7)) * 16);
            const __half* g = g_X16 + (size_t)(rowBase + r) * 1024 + k0 + s * 8;
            CPASYNC16(d, g);
        }
        #pragma unroll
        for (int it = 0; it < 4; it++) {
            int idx = tid + it * 512;
            int k = idx >> 5, s = idx & 31;
            uint32_t d = bufSm + IG_WH + k * 512 + swz32(s, k) * 16;
            const __half* g = WHi + (size_t)(k0 + k) * 1024 + colBase + s * 8;
            CPASYNC16(d, g);
            d = bufSm + IG_WL + k * 512 + swz32(s, k) * 16;
            g = WLo + (size_t)(k0 + k) * 1024 + colBase + s * 8;
            CPASYNC16(d, g);
        }
    };

    stage(0, sb + 0);
    CPCOMMIT();

    for (int c = 0; c < 16; c++) {
        const uint32_t cur = sb + (uint32_t)(c & 1) * IG_STG;
        if (c < 15) {
            stage(c + 1, sb + (uint32_t)((c + 1) & 1) * IG_STG);
            CPCOMMIT();
            CPWAIT1();
        } else {
            CPWAIT0();
        }
        __syncthreads();

        #pragma unroll
        for (int ks = 0; ks < 4; ks++) {
            uint32_t ah[2][4];
            #pragma unroll
            for (int i = 0; i < 2; i++) {
                int row = mw + i * 16 + (lane & 15);
                int s = ks * 2 + (lane >> 4);
                uint32_t ab = cur + IG_A + row * 128 + ((s ^ (row & 7)) * 16);
                ldsm_x4(ah[i], ab);
            }
            #pragma unroll
            for (int jp = 0; jp < 4; jp++) {
                int rrow = ks * 16 + (lane & 15);
                int sc = (nw >> 3) + jp * 2 + (lane >> 4);
                uint32_t bb = cur + rrow * 512 + swz32((uint32_t)sc, (uint32_t)rrow) * 16;
                uint32_t bh[4], bl[4];
                ldsm_x4t(bh, bb + IG_WH);
                ldsm_x4t(bl, bb + IG_WL);
                #pragma unroll
                for (int i = 0; i < 2; i++) {
                    mma16816h(acc[i][jp*2+0], ah[i], &bh[0]);
                    mma16816h(acc[i][jp*2+0], ah[i], &bl[0]);
                    mma16816h(acc[i][jp*2+1], ah[i], &bh[2]);
                    mma16816h(acc[i][jp*2+1], ah[i], &bl[2]);
                }
            }
        }
        __syncthreads();
    }

    const int g = lane >> 2, qn = (lane & 3) * 2;
    #pragma unroll
    for (int j = 0; j < 8; j++) {
        int col = colBase + nw + j * 8 + qn;
        float2 bv = *(const float2*)(bias + col);
        #pragma unroll
        for (int i = 0; i < 2; i++) {
            int r0 = rowBase + mw + i * 16 + g;
            *(float2*)(Out + (size_t)r0 * 1024 + col) =
                make_float2(acc[i][j][0] + bv.x, acc[i][j][1] + bv.y);
            *(float2*)(Out + (size_t)(r0 + 8) * 1024 + col) =
                make_float2(acc[i][j][2] + bv.x, acc[i][j][3] + bv.y);
        }
    }
}

// ---------------- recurrent kernel (persistent, 2x512-col chunks) ---------
// 128 blocks x 512 threads. Warps 0-7 compute (R warps 0-3, Z warps 4-7;
// H on warps 0-3); warps 8-15 poll+stream the two 512-col chunks.
__global__ void __launch_bounds__(512, 1) gru_recurrent(
    const float* __restrict__ state,
    const float* __restrict__ Whr, const float* __restrict__ Whz, const float* __restrict__ Whh,
    float* __restrict__ out)
{
    extern __shared__ char sm[];
    const uint32_t sb = smem_u32(sm);
    const int tid = threadIdx.x;
    const int lane = tid & 31, w = tid >> 5;
    const int bid = blockIdx.x;
    const int cB  = bid * CPB;
    const int mychunk = bid >> 6;      // 2 chunks, 64 blocks (256 warps) each
    const int cstart  = mychunk;       // staggered start chunk

    // ---- reset dataflow counters (block 0) ----
    if (bid == 0 && tid == 0) {
        #pragma unroll
        for (int c = 0; c < 2; c++) { g_cnt_h[c] = 256u; g_cnt_rh[c] = 0u; }
        g_p1done = 0u; g_p2done = 0u;
    }

    // ---- persistent W slabs: [k][8n] rows of 16B, single fp16 ----
    {
        const float* Wm[3] = { Whr, Whz, Whh };
        for (int idx = tid; idx < 8192; idx += 512) {
            int k = idx >> 3, n = idx & 7;
            #pragma unroll
            for (int m = 0; m < 3; m++) {
                float v = Wm[m][(size_t)k * 1024 + cB + n];
                *(__half*)(sm + RS_W + m * 16384 + k * 16 + n * 2) = __float2half_rn(v);
            }
        }
    }
    // ---- init h (buffer 0) ----
    if (tid < 512) {
        int r = tid >> 3, n = tid & 7;
        size_t gi = (size_t)r * 1024 + cB + n;
        float v = state[gi];
        g_h_f32[gi] = v;
        g_h16[0][gi] = __float2half_rn(v);
    }
    gridBarrier();   // publishes resets + weights + h0; the ONLY grid barrier

    const int m0  = (w & 3) * 16;
    const bool isR = (w < 4);
    const int g   = lane >> 2, qn = (lane & 3) * 2;
    const int r0  = m0 + g;
    const int col = cB + qn;
    const uint32_t wsel = sb + RS_W + (isR ? 0 : 1) * 16384;
    const uint32_t whh  = sb + RS_W + 2 * 16384;
    const int ptid = tid - 256;

    // producer: stream 512-col chunk c (64KB) into buffer c
    auto loadChunk = [&](const __half* src, int c) {
        char* buf = sm + RS_A + c * RS_ABUF;
        const int kbase = c * 512;
        #pragma unroll
        for (int it = 0; it < 16; it++) {
            int idx = ptid + it * 256;       // 0..4095 (64 rows x 64 segs)
            int r = idx >> 6, s = idx & 63;
            uint32_t off = (uint32_t)r * 1024 + swzg((uint32_t)s, (uint32_t)r) * 16;
            size_t go = (size_t)r * 1024 + kbase + s * 8;
            *(uint4*)(buf + off) = __ldcg((const uint4*)(src + go));
        }
    };
    // poll chunk-ready, then load (producer warps 8-15, 256 threads)
    auto pollLoad = [&](const __half* src, int c,
                        const unsigned* cnt, unsigned tgt) {
        if (w == 8) waitGE(cnt + c, tgt);
        asm volatile("bar.sync 1, 256;" ::: "memory");
        loadChunk(src, c);
    };
    // consume 512-col chunk c (buffer c) against W slab wBase
    auto mmaChunk = [&](float* acc, uint32_t wBase, int c) {
        const uint32_t abase = sb + RS_A + (uint32_t)c * RS_ABUF;
        const int arow = m0 + (lane & 15);
        #pragma unroll
        for (int ks2 = 0; ks2 < 16; ks2++) {
            uint32_t bh[4];
            uint32_t baddr = wBase + (uint32_t)(c * 512 + ks2 * 32 + lane) * 16;
            ldsm_x4t(bh, baddr);
            uint32_t s0 = (uint32_t)(ks2 * 4 + (lane >> 4));
            uint32_t s1 = s0 + 2;
            uint32_t a0 = abase + (uint32_t)arow * 1024 + swzg(s0, (uint32_t)arow) * 16;
            uint32_t a1 = abase + (uint32_t)arow * 1024 + swzg(s1, (uint32_t)arow) * 16;
            uint32_t ah0[4], ah1[4];
            ldsm_x4(ah0, a0);
            ldsm_x4(ah1, a1);
            mma16816h(acc, ah0, &bh[0]);
            mma16816h(acc, ah1, &bh[2]);
        }
    };

    for (int t = 0; t < TT; t++) {
        const unsigned tgt = 256u * (unsigned)(t + 1);
        const int p  = t & 3;          // read buffer (4-deep)
        const int pn = (t + 1) & 3;    // write buffer for h
        const size_t xoffB = (size_t)t * BH + (size_t)r0 * 1024 + col;

        // ================ phase 1: R (warps 0-3) / Z (warps 4-7) ==========
        float acc[4] = {0.f, 0.f, 0.f, 0.f};
        const __half* Hsrc = g_h16[p];
        float2 x1a, x1b;
        if (w < 8) {
            const float* Xsrc = isR ? g_Xr : g_Xz;
            x1a = __ldg((const float2*)(Xsrc + xoffB));
            x1b = __ldg((const float2*)(Xsrc + xoffB + 8 * 1024));
        }
        if (w >= 8) pollLoad(Hsrc, cstart, g_cnt_h, tgt);
        for (int c = 0; c < 2; c++) {
            __syncthreads();
            if (w < 8)      mmaChunk(acc, wsel, (cstart + c) & 1);
            else if (c < 1) pollLoad(Hsrc, cstart ^ 1, g_cnt_h, tgt);
            else if (tid == 256) red_rel_gpu(&g_p1done, 1u);   // all h reads done
        }
        // ---- epilogue 1 (per-warp early publish of Rh) ----
        if (w < 8) {
            size_t h0o = (size_t)r0 * 1024 + col, h1o = h0o + 8 * 1024;
            if (isR) {
                // WAR: Rh buf p last read in phase 2 of step t-4
                if (t >= 4) waitGE(&g_p2done, 128u * (unsigned)(t - 3));
                float2 h0 = *(const float2*)(g_h_f32 + h0o);
                float2 h1 = *(const float2*)(g_h_f32 + h1o);
                float a0 = sigf(x1a.x + acc[0]) * h0.x;
                float a1 = sigf(x1a.y + acc[1]) * h0.y;
                float a2 = sigf(x1b.x + acc[2]) * h1.x;
                float a3 = sigf(x1b.y + acc[3]) * h1.y;
                __stcg((uint32_t*)(g_Rh16[p] + h0o), packh(a0, a1));
                __stcg((uint32_t*)(g_Rh16[p] + h1o), packh(a2, a3));
                __syncwarp();
                if (lane == 0) red_rel_gpu(&g_cnt_rh[mychunk], 1u);
            } else {
                *(float2*)(sm + RS_Z + (r0 * 8 + qn) * 4) =
                    make_float2(sigf(x1a.x + acc[0]), sigf(x1a.y + acc[1]));
                *(float2*)(sm + RS_Z + ((r0 + 8) * 8 + qn) * 4) =
                    make_float2(sigf(x1b.x + acc[2]), sigf(x1b.y + acc[3]));
            }
        }

        // ================ phase 2: H_hat (warps 0-3) ======================
        float acch[4] = {0.f, 0.f, 0.f, 0.f};
        const __half* Rsrc = g_Rh16[p];
        float2 x2a, x2b;
        if (w < 4) {
            x2a = __ldg((const float2*)(g_Xh + xoffB));
            x2b = __ldg((const float2*)(g_Xh + xoffB + 8 * 1024));
        }
        if (w >= 8) pollLoad(Rsrc, cstart, g_cnt_rh, tgt);
        for (int c = 0; c < 2; c++) {
            __syncthreads();
            if (w < 4)      mmaChunk(acch, whh, (cstart + c) & 1);
            else if (w >= 8) {
                if (c < 1)  pollLoad(Rsrc, cstart ^ 1, g_cnt_rh, tgt);
                else if (tid == 256) red_rel_gpu(&g_p2done, 1u);  // all Rh reads done
            }
        }
        // ---- epilogue 2 (per-warp early publish of h) ----
        if (w < 4) {
            // WAR: h buf pn last written step t-4, read in phase 1 of step t-3
            if (t >= 3) waitGE(&g_p1done, 128u * (unsigned)(t - 2));
            size_t o0 = xoffB, o1 = xoffB + 8 * 1024;
            size_t h0o = (size_t)r0 * 1024 + col, h1o = h0o + 8 * 1024;
            float2 z0 = *(const float2*)(sm + RS_Z + (r0 * 8 + qn) * 4);
            float2 z1 = *(const float2*)(sm + RS_Z + ((r0 + 8) * 8 + qn) * 4);
            float2 h0 = *(const float2*)(g_h_f32 + h0o);
            float2 h1 = *(const float2*)(g_h_f32 + h1o);
            float n0 = z0.x * h0.x + (1.f - z0.x) * tanhf(x2a.x + acch[0]);
            float n1 = z0.y * h0.y + (1.f - z0.y) * tanhf(x2a.y + acch[1]);
            float n2 = z1.x * h1.x + (1.f - z1.x) * tanhf(x2b.x + acch[2]);
            float n3 = z1.y * h1.y + (1.f - z1.y) * tanhf(x2b.y + acch[3]);
            __stcg((uint32_t*)(g_h16[pn] + h0o), packh(n0, n1));
            __stcg((uint32_t*)(g_h16[pn] + h1o), packh(n2, n3));
            __syncwarp();
            if (lane == 0) red_rel_gpu(&g_cnt_h[mychunk], 1u);
            *(float2*)(out + o0) = make_float2(n0, n1);
            *(float2*)(out + o1) = make_float2(n2, n3);
            *(float2*)(g_h_f32 + h0o) = make_float2(n0, n1);
            *(float2*)(g_h_f32 + h1o) = make_float2(n2, n3);
            if (t == TT - 1) {
                size_t f0 = (size_t)TT * BH + h0o;
                *(float2*)(out + f0)            = make_float2(n0, n1);
                *(float2*)(out + f0 + 8 * 1024) = make_float2(n2, n3);
            }
        }
    }
}

// ---------------- launch ---------------------------------------------------
extern "C" void kernel_launch(void* const* d_in, const int* in_sizes, int n_in,
                              void* d_out, int out_size) {
    const float* X    = (const float*)d_in[0];
    const float* state= (const float*)d_in[1];
    const float* W_xr = (const float*)d_in[2];
    const float* W_hr = (const float*)d_in[3];
    const float* b_r  = (const float*)d_in[4];
    const float* W_xz = (const float*)d_in[5];
    const float* W_hz = (const float*)d_in[6];
    const float* b_z  = (const float*)d_in[7];
    const float* W_xh = (const float*)d_in[8];
    const float* W_hh = (const float*)d_in[9];
    const float* b_h  = (const float*)d_in[10];
    float* out = (float*)d_out;

    __half *x16, *whi, *wlo;
    cudaGetSymbolAddress((void**)&x16, g_X16);
    cudaGetSymbolAddress((void**)&whi, g_W16h);
    cudaGetSymbolAddress((void**)&wlo, g_W16l);

    split_h1<<<(TT * BB * DH / 4 + 255) / 256, 256>>>(X, x16, TT * BB * DH / 4);
    split_h2<<<(1048576 / 4 + 255) / 256, 256>>>(W_xr, whi, wlo, 1048576 / 4);
    split_h2<<<(1048576 / 4 + 255) / 256, 256>>>(W_xz, whi + 1048576, wlo + 1048576, 1048576 / 4);
    split_h2<<<(1048576 / 4 + 255) / 256, 256>>>(W_xh, whi + 2097152, wlo + 2097152, 1048576 / 4);

    cudaFuncSetAttribute(input_gemm,
                         cudaFuncAttributeMaxDynamicSharedMemorySize, IG_TOT);
    dim3 g1(4, 256, 3);
    input_gemm<<<g1, 512, IG_TOT>>>(b_r, b_z, b_h);

    cudaFuncSetAttribute(gru_recurrent,
                         cudaFuncAttributeMaxDynamicSharedMemorySize, RS_TOT);
    gru_recurrent<<<NB, 512, RS_TOT>>>(state, W_hr, W_hz, W_hh, out);
}

// round 16
// speedup vs baseline: 1.0495x; 1.0495x over previous
#include <cuda_runtime.h>
#include <cuda_bf16.h>
#include <cuda_fp16.h>
#include <math.h>
#include <stdint.h>

#define TT 512
#define BB 64
#define DH 1024
#define BH (BB*DH)
#define NB 128          // persistent blocks, 1/SM
#define CPB 8           // hidden columns per block

// ---------------- recurrent kernel SMEM layout (bytes) --------------------
// W slabs: 3 x 16384 (WR, WZ, WH) single fp16
#define RS_W    0
#define RS_A    49152      // 2 buffers x 32768 (fp16 h chunk: 64 rows x 512B)
#define RS_ABUF 32768
#define RS_Z    114688     // z gate buf 64x8 f32
#define RS_TOT  116736

// ---------------- input gemm SMEM layout (bytes, per stage) ---------------
#define IG_A    0          // X fp16: 128 rows x 128B
#define IG_WH   16384      // W hi fp16: 64 rows x 512B
#define IG_WL   49152      // W lo fp16
#define IG_STG  81920
#define IG_TOT  163840

// ---------------- device globals ------------------------------------------
__device__ __half g_Xr[(size_t)TT * BH];
__device__ __half g_Xz[(size_t)TT * BH];
__device__ __half g_Xh[(size_t)TT * BH];
__device__ __half g_X16[(size_t)TT * BB * DH];
__device__ __half g_W16h[3u * 1024u * 1024u];
__device__ __half g_W16l[3u * 1024u * 1024u];
__device__ float g_h_f32[BH];
__device__ __half g_h16[4][BH];      // 4-deep h exchange buffers (fp16)
__device__ __half g_Rh16[4][BH];     // 4-deep Rh exchange buffers (fp16)
__device__ unsigned g_cnt_h[4];      // h-warp-publish counters, per 256-col k-chunk
__device__ unsigned g_cnt_rh[4];     // Rh-warp-publish counters, per k-chunk
__device__ unsigned g_p1done;        // blocks done reading h (phase 1)
__device__ unsigned g_p2done;        // blocks done reading Rh (phase 2)
__device__ unsigned g_bar_count = 0;
__device__ volatile unsigned g_bar_gen = 0;

// ---------------- helpers -------------------------------------------------
__device__ __forceinline__ uint32_t smem_u32(const void* p) {
    uint32_t a;
    asm("{ .reg .u64 t; cvta.to.shared.u64 t, %1; cvt.u32.u64 %0, t; }" : "=r"(a) : "l"(p));
    return a;
}
__device__ __forceinline__ void mma16816h(float* c, const uint32_t* a, const uint32_t* b) {
    asm volatile("mma.sync.aligned.m16n8k16.row.col.f32.f16.f16.f32 "
        "{%0,%1,%2,%3}, {%4,%5,%6,%7}, {%8,%9}, {%0,%1,%2,%3};"
        : "+f"(c[0]), "+f"(c[1]), "+f"(c[2]), "+f"(c[3])
        : "r"(a[0]), "r"(a[1]), "r"(a[2]), "r"(a[3]), "r"(b[0]), "r"(b[1]));
}
__device__ __forceinline__ void ldsm_x4(uint32_t* r, uint32_t a) {
    asm volatile("ldmatrix.sync.aligned.m8n8.x4.shared.b16 {%0,%1,%2,%3}, [%4];"
        : "=r"(r[0]), "=r"(r[1]), "=r"(r[2]), "=r"(r[3]) : "r"(a));
}
__device__ __forceinline__ void ldsm_x4t(uint32_t* r, uint32_t a) {
    asm volatile("ldmatrix.sync.aligned.m8n8.x4.trans.shared.b16 {%0,%1,%2,%3}, [%4];"
        : "=r"(r[0]), "=r"(r[1]), "=r"(r[2]), "=r"(r[3]) : "r"(a));
}
#define CPASYNC16(dst, src) asm volatile("cp.async.cg.shared.global [%0], [%1], 16;" :: "r"(dst), "l"(src))
#define CPCOMMIT() asm volatile("cp.async.commit_group;" ::: "memory")
#define CPWAIT1()  asm volatile("cp.async.wait_group 1;" ::: "memory")
#define CPWAIT0()  asm volatile("cp.async.wait_group 0;" ::: "memory")

__device__ __forceinline__ unsigned ld_acq_g(const unsigned* p) {
    unsigned v;
    asm volatile("ld.acquire.gpu.global.u32 %0, [%1];" : "=r"(v) : "l"(p) : "memory");
    return v;
}
__device__ __forceinline__ void waitGE(const unsigned* p, unsigned tgt) {
    while ((int)(ld_acq_g(p) - tgt) < 0) { }
}
__device__ __forceinline__ void red_rel_gpu(unsigned* p, unsigned v) {
    asm volatile("red.release.gpu.global.add.u32 [%0], %1;" :: "l"(p), "r"(v) : "memory");
}

__device__ __forceinline__ uint32_t packh(float x, float y) {
    __half2 hh = __floats2half2_rn(x, y);
    return *(uint32_t*)&hh;
}
__device__ __forceinline__ float2 h2f2(__half2 h) {
    return __half22float2(h);
}
__device__ __forceinline__ float sigf(float x) { return 1.0f / (1.0f + expf(-x)); }
__device__ __forceinline__ uint32_t swz32(uint32_t s, uint32_t r) {
    return ((s & 7u) ^ (r & 7u)) | (s & 24u);
}

// ---------------- grid barrier (init only) --------------------------------
__device__ __forceinline__ void gridBarrier() {
    __syncthreads();
    if (threadIdx.x == 0) {
        __threadfence();
        unsigned g = g_bar_gen;
        if (atomicAdd(&g_bar_count, 1u) == (unsigned)(NB - 1)) {
            g_bar_count = 0;
            __threadfence();
            g_bar_gen = g + 1;
        } else {
            while (g_bar_gen == g) { }
        }
        __threadfence();
    }
    __syncthreads();
}

// ---------------- prepass: fp32 -> fp16 single ----------------------------
__global__ void __launch_bounds__(256) split_h1(
    const float* __restrict__ src, __half* __restrict__ dst, int n4)
{
    int i = blockIdx.x * 256 + threadIdx.x;
    if (i >= n4) return;
    float4 v = __ldg((const float4*)src + i);
    ((uint2*)dst)[i] = make_uint2(packh(v.x, v.y), packh(v.z, v.w));
}

// ---------------- prepass: fp32 -> fp16 hi/lo split -----------------------
__global__ void __launch_bounds__(256) split_h2(
    const float* __restrict__ src, __half* __restrict__ hi,
    __half* __restrict__ lo, int n4)
{
    int i = blockIdx.x * 256 + threadIdx.x;
    if (i >= n4) return;
    float4 v = __ldg((const float4*)src + i);
    float f[4] = { v.x, v.y, v.z, v.w };
    uint32_t hh[2], ll[2];
    #pragma unroll
    for (int q = 0; q < 2; q++) {
        __half h0 = __float2half_rn(f[q*2]),   h1 = __float2half_rn(f[q*2+1]);
        __half l0 = __float2half_rn(f[q*2]   - __half2float(h0));
        __half l1 = __float2half_rn(f[q*2+1] - __half2float(h1));
        __half2 ph = __halves2half2(h0, h1), pl = __halves2half2(l0, l1);
        hh[q] = *(uint32_t*)&ph; ll[q] = *(uint32_t*)&pl;
    }
    ((uint2*)hi)[i] = make_uint2(hh[0], hh[1]);
    ((uint2*)lo)[i] = make_uint2(ll[0], ll[1]);
}

// ---------------- input projection GEMM (fp16 HMMA, cp.async pipeline) ----
__global__ void __launch_bounds__(512, 1) input_gemm(
    const float* __restrict__ br, const float* __restrict__ bz, const float* __restrict__ bh)
{
    extern __shared__ char sm[];
    const uint32_t sb = smem_u32(sm);
    const int z = blockIdx.z;
    const float* bias = (z == 0) ? br : (z == 1) ? bz : bh;
    __half* Out = (z == 0) ? g_Xr : (z == 1) ? g_Xz : g_Xh;
    const __half* WHi = g_W16h + (size_t)z * 1048576u;
    const __half* WLo = g_W16l + (size_t)z * 1048576u;

    const int tid = threadIdx.x;
    const int lane = tid & 31, w = tid >> 5;
    const int rowBase = blockIdx.y * 128;
    const int colBase = blockIdx.x * 256;
    const int mw = (w & 3) * 32;
    const int nw = (w >> 2) * 64;

    float acc[2][8][4];
    #pragma unroll
    for (int i = 0; i < 2; i++)
        #pragma unroll
        for (int j = 0; j < 8; j++)
            #pragma unroll
            for (int q = 0; q < 4; q++) acc[i][j][q] = 0.f;

    auto stage = [&](int c, uint32_t bufSm) {
        const int k0 = c * 64;
        #pragma unroll
        for (int it = 0; it < 2; it++) {
            int idx = tid + it * 512;
            int r = idx >> 3, s = idx & 7;
            uint32_t d = bufSm + IG_A + r * 128 + ((s ^ (r & 7)) * 16);
            const __half* g = g_X16 + (size_t)(rowBase + r) * 1024 + k0 + s * 8;
            CPASYNC16(d, g);
        }
        #pragma unroll
        for (int it = 0; it < 4; it++) {
            int idx = tid + it * 512;
            int k = idx >> 5, s = idx & 31;
            uint32_t d = bufSm + IG_WH + k * 512 + swz32(s, k) * 16;
            const __half* g = WHi + (size_t)(k0 + k) * 1024 + colBase + s * 8;
            CPASYNC16(d, g);
            d = bufSm + IG_WL + k * 512 + swz32(s, k) * 16;
            g = WLo + (size_t)(k0 + k) * 1024 + colBase + s * 8;
            CPASYNC16(d, g);
        }
    };

    stage(0, sb + 0);
    CPCOMMIT();

    for (int c = 0; c < 16; c++) {
        const uint32_t cur = sb + (uint32_t)(c & 1) * IG_STG;
        if (c < 15) {
            stage(c + 1, sb + (uint32_t)((c + 1) & 1) * IG_STG);
            CPCOMMIT();
            CPWAIT1();
        } else {
            CPWAIT0();
        }
        __syncthreads();

        #pragma unroll
        for (int ks = 0; ks < 4; ks++) {
            uint32_t ah[2][4];
            #pragma unroll
            for (int i = 0; i < 2; i++) {
                int row = mw + i * 16 + (lane & 15);
                int s = ks * 2 + (lane >> 4);
                uint32_t ab = cur + IG_A + row * 128 + ((s ^ (row & 7)) * 16);
                ldsm_x4(ah[i], ab);
            }
            #pragma unroll
            for (int jp = 0; jp < 4; jp++) {
                int rrow = ks * 16 + (lane & 15);
                int sc = (nw >> 3) + jp * 2 + (lane >> 4);
                uint32_t bb = cur + rrow * 512 + swz32((uint32_t)sc, (uint32_t)rrow) * 16;
                uint32_t bh[4], bl[4];
                ldsm_x4t(bh, bb + IG_WH);
                ldsm_x4t(bl, bb + IG_WL);
                #pragma unroll
                for (int i = 0; i < 2; i++) {
                    mma16816h(acc[i][jp*2+0], ah[i], &bh[0]);
                    mma16816h(acc[i][jp*2+0], ah[i], &bl[0]);
                    mma16816h(acc[i][jp*2+1], ah[i], &bh[2]);
                    mma16816h(acc[i][jp*2+1], ah[i], &bl[2]);
                }
            }
        }
        __syncthreads();
    }

    const int g = lane >> 2, qn = (lane & 3) * 2;
    #pragma unroll
    for (int j = 0; j < 8; j++) {
        int col = colBase + nw + j * 8 + qn;
        float2 bv = *(const float2*)(bias + col);
        #pragma unroll
        for (int i = 0; i < 2; i++) {
            int r0 = rowBase + mw + i * 16 + g;
            *(uint32_t*)(Out + (size_t)r0 * 1024 + col) =
                packh(acc[i][j][0] + bv.x, acc[i][j][1] + bv.y);
            *(uint32_t*)(Out + (size_t)(r0 + 8) * 1024 + col) =
                packh(acc[i][j][2] + bv.x, acc[i][j][3] + bv.y);
        }
    }
}

// ---------------- recurrent kernel (persistent, per-warp early publish) ---
// 128 blocks x 512 threads. Warps 0-7 compute; warps 8-15 poll+stream chunks
// via cp.async. Publishing warps release their slice + counter immediately.
__global__ void __launch_bounds__(512, 1) gru_recurrent(
    const float* __restrict__ state,
    const float* __restrict__ Whr, const float* __restrict__ Whz, const float* __restrict__ Whh,
    float* __restrict__ out)
{
    extern __shared__ char sm[];
    const uint32_t sb = smem_u32(sm);
    const int tid = threadIdx.x;
    const int lane = tid & 31, w = tid >> 5;
    const int bid = blockIdx.x;
    const int cB  = bid * CPB;
    const int mychunk = bid >> 5;      // 4 chunks, 32 blocks (128 warps) each
    const int cstart  = mychunk;       // staggered start chunk

    // ---- reset dataflow counters (block 0) ----
    if (bid == 0 && tid == 0) {
        #pragma unroll
        for (int c = 0; c < 4; c++) { g_cnt_h[c] = 128u; g_cnt_rh[c] = 0u; }
        g_p1done = 0u; g_p2done = 0u;
    }

    // ---- persistent W slabs: [k][8n] rows of 16B, single fp16 ----
    {
        const float* Wm[3] = { Whr, Whz, Whh };
        for (int idx = tid; idx < 8192; idx += 512) {
            int k = idx >> 3, n = idx & 7;
            #pragma unroll
            for (int m = 0; m < 3; m++) {
                float v = Wm[m][(size_t)k * 1024 + cB + n];
                *(__half*)(sm + RS_W + m * 16384 + k * 16 + n * 2) = __float2half_rn(v);
            }
        }
    }
    // ---- init h (buffer 0) ----
    if (tid < 512) {
        int r = tid >> 3, n = tid & 7;
        size_t gi = (size_t)r * 1024 + cB + n;
        float v = state[gi];
        g_h_f32[gi] = v;
        g_h16[0][gi] = __float2half_rn(v);
    }
    gridBarrier();   // publishes resets + weights + h0; the ONLY grid barrier

    const int m0  = (w & 3) * 16;
    const bool isR = (w < 4);
    const int g   = lane >> 2, qn = (lane & 3) * 2;
    const int r0  = m0 + g;
    const int col = cB + qn;
    const uint32_t wsel = sb + RS_W + (isR ? 0 : 1) * 16384;
    const uint32_t whh  = sb + RS_W + 2 * 16384;
    const int ptid = tid - 256;

    // producer: stream chunk c into buffer b via cp.async (no reg round-trip)
    auto loadChunk = [&](const __half* src, int c, int b) {
        const uint32_t bufSm = sb + RS_A + (uint32_t)b * RS_ABUF;
        const int kbase = c * 256;
        #pragma unroll
        for (int it = 0; it < 8; it++) {
            int idx = ptid + it * 256;       // 0..2047 (64 rows x 32 segs)
            int r = idx >> 5, s = idx & 31;
            uint32_t off = (uint32_t)r * 512 + swz32((uint32_t)s, (uint32_t)r) * 16;
            size_t go = (size_t)r * 1024 + kbase + s * 8;
            CPASYNC16(bufSm + off, src + go);
        }
        CPCOMMIT();
        CPWAIT0();
    };
    // poll chunk-ready, then load (producer warps 8-15, 256 threads)
    auto pollLoad = [&](const __half* src, int c, int b,
                        const unsigned* cnt, unsigned tgt) {
        if (w == 8) waitGE(cnt + c, tgt);
        asm volatile("bar.sync 1, 256;" ::: "memory");
        loadChunk(src, c, b);
    };
    // consume chunk with k-offset of chunk id c from buffer b (single fp16 W)
    auto mmaChunk = [&](float* acc, int b, uint32_t wBase, int c) {
        const uint32_t abase = sb + RS_A + (uint32_t)b * RS_ABUF;
        const int arow = m0 + (lane & 15);
        #pragma unroll
        for (int ks2 = 0; ks2 < 8; ks2++) {
            uint32_t bh[4];
            uint32_t baddr = wBase + (uint32_t)(c * 256 + ks2 * 32 + lane) * 16;
            ldsm_x4t(bh, baddr);
            int s0 = ks2 * 4 + (lane >> 4);
            int s1 = s0 + 2;
            uint32_t a0 = abase + (uint32_t)arow * 512 + swz32((uint32_t)s0, (uint32_t)arow) * 16;
            uint32_t a1 = abase + (uint32_t)arow * 512 + swz32((uint32_t)s1, (uint32_t)arow) * 16;
            uint32_t ah0[4], ah1[4];
            ldsm_x4(ah0, a0);
            ldsm_x4(ah1, a1);
            mma16816h(acc, ah0, &bh[0]);
            mma16816h(acc, ah1, &bh[2]);
        }
    };

    for (int t = 0; t < TT; t++) {
        const unsigned tgt = 128u * (unsigned)(t + 1);
        const int p  = t & 3;          // read buffer (4-deep)
        const int pn = (t + 1) & 3;    // write buffer for h
        const size_t xoffB = (size_t)t * BH + (size_t)r0 * 1024 + col;

        // ================ phase 1: R (warps 0-3) / Z (warps 4-7) ==========
        float acc[4] = {0.f, 0.f, 0.f, 0.f};
        const __half* Hsrc = g_h16[p];
        // prefetch epilogue-1 X inputs (hidden under the MMA loop)
        float2 x1a, x1b;
        if (w < 8) {
            const __half* Xsrc = isR ? g_Xr : g_Xz;
            x1a = h2f2(__ldg((const __half2*)(Xsrc + xoffB)));
            x1b = h2f2(__ldg((const __half2*)(Xsrc + xoffB + 8 * 1024)));
        }
        if (w >= 8) pollLoad(Hsrc, cstart, 0, g_cnt_h, tgt);
        for (int c = 0; c < 4; c++) {
            __syncthreads();
            if (w < 8)      mmaChunk(acc, c & 1, wsel, (cstart + c) & 3);
            else if (c < 3) pollLoad(Hsrc, (cstart + c + 1) & 3, (c + 1) & 1, g_cnt_h, tgt);
            else if (tid == 256) red_rel_gpu(&g_p1done, 1u);   // all h reads done
        }
        // ---- epilogue 1 (per-warp early publish of Rh) ----
        if (w < 8) {
            size_t h0o = (size_t)r0 * 1024 + col, h1o = h0o + 8 * 1024;
            if (isR) {
                // WAR: Rh buf p last read in phase 2 of step t-4
                if (t >= 4) waitGE(&g_p2done, 128u * (unsigned)(t - 3));
                float2 h0 = *(const float2*)(g_h_f32 + h0o);
                float2 h1 = *(const float2*)(g_h_f32 + h1o);
                float a0 = sigf(x1a.x + acc[0]) * h0.x;
                float a1 = sigf(x1a.y + acc[1]) * h0.y;
                float a2 = sigf(x1b.x + acc[2]) * h1.x;
                float a3 = sigf(x1b.y + acc[3]) * h1.y;
                __stcg((uint32_t*)(g_Rh16[p] + h0o), packh(a0, a1));
                __stcg((uint32_t*)(g_Rh16[p] + h1o), packh(a2, a3));
                __syncwarp();
                if (lane == 0) red_rel_gpu(&g_cnt_rh[mychunk], 1u);
            } else {
                *(float2*)(sm + RS_Z + (r0 * 8 + qn) * 4) =
                    make_float2(sigf(x1a.x + acc[0]), sigf(x1a.y + acc[1]));
                *(float2*)(sm + RS_Z + ((r0 + 8) * 8 + qn) * 4) =
                    make_float2(sigf(x1b.x + acc[2]), sigf(x1b.y + acc[3]));
            }
        }

        // ================ phase 2: H_hat (warps 0-3) ======================
        float acch[4] = {0.f, 0.f, 0.f, 0.f};
        const __half* Rsrc = g_Rh16[p];
        float2 x2a, x2b;
        if (w < 4) {
            x2a = h2f2(__ldg((const __half2*)(g_Xh + xoffB)));
            x2b = h2f2(__ldg((const __half2*)(g_Xh + xoffB + 8 * 1024)));
        }
        if (w >= 8) pollLoad(Rsrc, cstart, 0, g_cnt_rh, tgt);
        for (int c = 0; c < 4; c++) {
            __syncthreads();
            if (w < 4)      mmaChunk(acch, c & 1, whh, (cstart + c) & 3);
            else if (w >= 8) {
                if (c < 3)  pollLoad(Rsrc, (cstart + c + 1) & 3, (c + 1) & 1, g_cnt_rh, tgt);
                else if (tid == 256) red_rel_gpu(&g_p2done, 1u);  // all Rh reads done
            }
        }
        // ---- epilogue 2 (per-warp early publish of h) ----
        if (w < 4) {
            // WAR: h buf pn last written step t-4, read in phase 1 of step t-3
            if (t >= 3) waitGE(&g_p1done, 128u * (unsigned)(t - 2));
            size_t o0 = xoffB, o1 = xoffB + 8 * 1024;
            size_t h0o = (size_t)r0 * 1024 + col, h1o = h0o + 8 * 1024;
            float2 z0 = *(const float2*)(sm + RS_Z + (r0 * 8 + qn) * 4);
            float2 z1 = *(const float2*)(sm + RS_Z + ((r0 + 8) * 8 + qn) * 4);
            float2 h0 = *(const float2*)(g_h_f32 + h0o);
            float2 h1 = *(const float2*)(g_h_f32 + h1o);
            float n0 = z0.x * h0.x + (1.f - z0.x) * tanhf(x2a.x + acch[0]);
            float n1 = z0.y * h0.y + (1.f - z0.y) * tanhf(x2a.y + acch[1]);
            float n2 = z1.x * h1.x + (1.f - z1.x) * tanhf(x2b.x + acch[2]);
            float n3 = z1.y * h1.y + (1.f - z1.y) * tanhf(x2b.y + acch[3]);
            __stcg((uint32_t*)(g_h16[pn] + h0o), packh(n0, n1));
            __stcg((uint32_t*)(g_h16[pn] + h1o), packh(n2, n3));
            __syncwarp();
            if (lane == 0) red_rel_gpu(&g_cnt_h[mychunk], 1u);
            *(float2*)(out + o0) = make_float2(n0, n1);
            *(float2*)(out + o1) = make_float2(n2, n3);
            *(float2*)(g_h_f32 + h0o) = make_float2(n0, n1);
            *(float2*)(g_h_f32 + h1o) = make_float2(n2, n3);
            if (t == TT - 1) {
                size_t f0 = (size_t)TT * BH + h0o;
                *(float2*)(out + f0)            = make_float2(n0, n1);
                *(float2*)(out + f0 + 8 * 1024) = make_float2(n2, n3);
            }
        }
    }
}

// ---------------- launch ---------------------------------------------------
extern "C" void kernel_launch(void* const* d_in, const int* in_sizes, int n_in,
                              void* d_out, int out_size) {
    const float* X    = (const float*)d_in[0];
    const float* state= (const float*)d_in[1];
    const float* W_xr = (const float*)d_in[2];
    const float* W_hr = (const float*)d_in[3];
    const float* b_r  = (const float*)d_in[4];
    const float* W_xz = (const float*)d_in[5];
    const float* W_hz = (const float*)d_in[6];
    const float* b_z  = (const float*)d_in[7];
    const float* W_xh = (const float*)d_in[8];
    const float* W_hh = (const float*)d_in[9];
    const float* b_h  = (const float*)d_in[10];
    float* out = (float*)d_out;

    __half *x16, *whi, *wlo;
    cudaGetSymbolAddress((void**)&x16, g_X16);
    cudaGetSymbolAddress((void**)&whi, g_W16h);
    cudaGetSymbolAddress((void**)&wlo, g_W16l);

    split_h1<<<(TT * BB * DH / 4 + 255) / 256, 256>>>(X, x16, TT * BB * DH / 4);
    split_h2<<<(1048576 / 4 + 255) / 256, 256>>>(W_xr, whi, wlo, 1048576 / 4);
    split_h2<<<(1048576 / 4 + 255) / 256, 256>>>(W_xz, whi + 1048576, wlo + 1048576, 1048576 / 4);
    split_h2<<<(1048576 / 4 + 255) / 256, 256>>>(W_xh, whi + 2097152, wlo + 2097152, 1048576 / 4);

    cudaFuncSetAttribute(input_gemm,
                         cudaFuncAttributeMaxDynamicSharedMemorySize, IG_TOT);
    dim3 g1(4, 256, 3);
    input_gemm<<<g1, 512, IG_TOT>>>(b_r, b_z, b_h);

    cudaFuncSetAttribute(gru_recurrent,
                         cudaFuncAttributeMaxDynamicSharedMemorySize, RS_TOT);
    gru_recurrent<<<NB, 512, RS_TOT>>>(state, W_hr, W_hz, W_hh, out);
}